// round 11
// baseline (speedup 1.0000x reference)
#include <cuda_runtime.h>
#include <cuda_bf16.h>
#include <cstdint>

// EdgeModel fused 3-layer MLP via arch-agnostic mma.sync (bf16 3-term split).
// R10: single CTA/SM with internalized overlap. 512 threads (16 warps,
// warp tile 32x16). Double-buffered B via cp.async (copy c+1 during MMA c),
// layer-0 A chunks prefetched into registers under the MMA shadow.
// SMEM = A(34.8K) + 2x B(69.6K) = 170KB -> 1 CTA/SM.

#define DH 128
#define TM 64
#define APAD 68
#define A_U32 (TM * APAD)             // 4352
#define B_U32 (128 * APAD)            // 8704
#define BREG_BYTES (2 * B_U32 * 4)    // 69632 (hi+lo, one region)
#define SMEM_TOTAL (2 * A_U32 * 4 + 2 * BREG_BYTES)   // 174080

// weight images: 5 regions (W0 k-chunks 0..2, W1, W2) x {hi,lo} x [n][kp]
__device__ __align__(16) uint32_t g_wp[5][2][128][APAD];

// ---------------- helpers ----------------
__device__ __forceinline__ uint32_t smem_u32(const void* p) {
    uint32_t a;
    asm("{ .reg .u64 t; cvta.to.shared.u64 t, %1; cvt.u32.u64 %0, t; }"
        : "=r"(a) : "l"(p));
    return a;
}

__device__ __forceinline__ uint32_t pack_bf2(float a0, float a1, uint32_t* lo_out) {
    __nv_bfloat16 h0 = __float2bfloat16(a0);
    __nv_bfloat16 h1 = __float2bfloat16(a1);
    __nv_bfloat16 l0 = __float2bfloat16(a0 - __bfloat162float(h0));
    __nv_bfloat16 l1 = __float2bfloat16(a1 - __bfloat162float(h1));
    *lo_out = (uint32_t)__bfloat16_as_ushort(l0) |
              ((uint32_t)__bfloat16_as_ushort(l1) << 16);
    return (uint32_t)__bfloat16_as_ushort(h0) |
           ((uint32_t)__bfloat16_as_ushort(h1) << 16);
}

__device__ __forceinline__ float silu_f(float x) {
    return x / (1.0f + __expf(-x));
}

#define LDSM4(r, addr)                                                         \
    asm volatile("ldmatrix.sync.aligned.m8n8.x4.shared.b16 {%0,%1,%2,%3}, [%4];" \
        : "=r"((r)[0]), "=r"((r)[1]), "=r"((r)[2]), "=r"((r)[3]) : "r"(addr))

#define MMA16816(c, a, b)                                                      \
    asm volatile("mma.sync.aligned.m16n8k16.row.col.f32.bf16.bf16.f32 "        \
        "{%0,%1,%2,%3}, {%4,%5,%6,%7}, {%8,%9}, {%0,%1,%2,%3};"                \
        : "+f"((c)[0]), "+f"((c)[1]), "+f"((c)[2]), "+f"((c)[3])               \
        : "r"((a)[0]), "r"((a)[1]), "r"((a)[2]), "r"((a)[3]),                  \
          "r"((b)[0]), "r"((b)[1]))

#define CP_ASYNC16(sm_addr, gptr)                                              \
    asm volatile("cp.async.cg.shared.global [%0], [%1], 16;"                   \
        :: "r"(sm_addr), "l"(gptr) : "memory")
#define CP_COMMIT()  asm volatile("cp.async.commit_group;" ::: "memory")
#define CP_WAIT1()   asm volatile("cp.async.wait_group 1;" ::: "memory")
#define CP_WAIT0()   asm volatile("cp.async.wait_group 0;" ::: "memory")

// ---------------- prep: pack weights into hi/lo ldmatrix-ready images -------
__global__ void prep_weights(const float* __restrict__ W0,
                             const float* __restrict__ W1,
                             const float* __restrict__ W2) {
    int i = blockIdx.x * blockDim.x + threadIdx.x;
    if (i >= 5 * 128 * 64) return;
    int r   = i >> 13;
    int rem = i & 8191;
    int n   = rem >> 6;
    int kp  = rem & 63;
    const float* W = (r < 3) ? W0 : (r == 3) ? W1 : W2;
    int k0 = ((r < 3) ? r * 128 : 0) + 2 * kp;
    float v0 = W[(size_t)k0 * DH + n];
    float v1 = W[(size_t)(k0 + 1) * DH + n];
    uint32_t lo;
    uint32_t hi = pack_bf2(v0, v1, &lo);
    g_wp[r][0][n][kp] = hi;
    g_wp[r][1][n][kp] = lo;
}

// ---------------- device pieces ----------------
__device__ __forceinline__ void copyB(uint32_t dstb, const uint4* s, int tid) {
    #pragma unroll 1
    for (int i = tid; i < 2 * B_U32 / 4; i += 512)
        CP_ASYNC16(dstb + i * 16, s + i);
    CP_COMMIT();
}

// prefetch one layer-0 A chunk into regs; volatile ld pins issue before MMAs
__device__ __forceinline__ void pf_load(float4 pf[4], const float* base) {
    #pragma unroll
    for (int q = 0; q < 4; q++)
        asm volatile("ld.global.nc.v4.f32 {%0,%1,%2,%3}, [%4];"
            : "=f"(pf[q].x), "=f"(pf[q].y), "=f"(pf[q].z), "=f"(pf[q].w)
            : "l"(base + q * 4));
}

__device__ __forceinline__ void storeA(uint32_t* Ahi, uint32_t* Alo,
                                       const float4 pf[4], int srow, int sq,
                                       bool sv) {
    #pragma unroll
    for (int q = 0; q < 4; q++) {
        float4 v = pf[q];
        if (!sv) v = make_float4(0.f, 0.f, 0.f, 0.f);
        uint32_t lo0, lo1;
        uint32_t h0 = pack_bf2(v.x, v.y, &lo0);
        uint32_t h1 = pack_bf2(v.z, v.w, &lo1);
        int kp = sq * 8 + 2 * q;
        Ahi[srow * APAD + kp]     = h0;
        Ahi[srow * APAD + kp + 1] = h1;
        Alo[srow * APAD + kp]     = lo0;
        Alo[srow * APAD + kp + 1] = lo1;
    }
}

__device__ __forceinline__ void mma_chunk(float acc[2][2][4],
                                          uint32_t aHiL, uint32_t aLoL,
                                          uint32_t bHiL, uint32_t bLoL) {
    #pragma unroll 2
    for (int ks = 0; ks < 8; ks++) {
        uint32_t ah[2][4], al[2][4], bh[4], bl[4];
        #pragma unroll
        for (int mt = 0; mt < 2; mt++) {
            uint32_t off = mt * (16 * APAD * 4) + ks * 32;
            LDSM4(ah[mt], aHiL + off);
            LDSM4(al[mt], aLoL + off);
        }
        LDSM4(bh, bHiL + ks * 32);
        LDSM4(bl, bLoL + ks * 32);
        #pragma unroll
        for (int mt = 0; mt < 2; mt++)
            #pragma unroll
            for (int nt = 0; nt < 2; nt++) {
                MMA16816(acc[mt][nt], ah[mt], &bh[nt * 2]);   // Ah*Bh
                MMA16816(acc[mt][nt], al[mt], &bh[nt * 2]);   // Al*Bh
                MMA16816(acc[mt][nt], ah[mt], &bl[nt * 2]);   // Ah*Bl
            }
    }
}

// ---------------- fused MLP kernel ----------------
__global__ void __launch_bounds__(512)
mlp_kernel(const float* __restrict__ src, const float* __restrict__ dst,
           const float* __restrict__ edg,
           const float* __restrict__ b0, const float* __restrict__ b1,
           const float* __restrict__ b2,
           float* __restrict__ out, int E)
{
    extern __shared__ uint32_t sm[];
    uint32_t* Ahi = sm;
    uint32_t* Alo = sm + A_U32;
    const uint32_t smb   = smem_u32(sm);
    const uint32_t aHiB  = smb;
    const uint32_t aLoB  = smb + A_U32 * 4;
    const uint32_t bB[2] = { smb + 2 * A_U32 * 4,
                             smb + 2 * A_U32 * 4 + BREG_BYTES };

    const int tid = threadIdx.x;
    const int l = tid & 31, w = tid >> 5;
    const int warp_m = (w & 1) * 32;
    const int warp_n = (w >> 1) * 16;
    const int tile = blockIdx.x;

    // ldmatrix per-lane offsets (verified mapping, R8/R9)
    const int laneA_r = (l & 7) + ((l >> 3) & 1) * 8;
    const int laneA_k = ((l >> 4) & 1) * 4;
    const int laneB_r = (l & 7) + ((l >> 4) & 1) * 8;
    const int laneB_k = ((l >> 3) & 1) * 4;
    const uint32_t aoff = ((warp_m + laneA_r) * APAD + laneA_k) * 4;
    const uint32_t boff = ((warp_n + laneB_r) * APAD + laneB_k) * 4;
    const uint32_t aHiL = aHiB + aoff, aLoL = aLoB + aoff;
    const uint32_t bHiL[2] = { bB[0] + boff, bB[1] + boff };
    const uint32_t bLoL[2] = { bB[0] + B_U32 * 4 + boff, bB[1] + B_U32 * 4 + boff };

    float acc[2][2][4];
    #pragma unroll
    for (int mt = 0; mt < 2; mt++)
        #pragma unroll
        for (int nt = 0; nt < 2; nt++)
            #pragma unroll
            for (int q = 0; q < 4; q++) acc[mt][nt][q] = 0.f;

    // A staging map: 512 thr -> (row 0..63, 16-col slice)
    const int srow = tid >> 3, sq = tid & 7;
    const int grow_s = tile * TM + srow;
    const bool svalid = grow_s < E;
    const size_t arow = (size_t)(svalid ? grow_s : 0) * DH + sq * 16;

    // epilogue lane constants (same formulas as R9, nt<2)
    const int er0 = (l >> 2);
    const int ec  = (l & 3) * 2;
    const int ecp = (warp_n >> 1) + (l & 3);

    float4 pf[4];

    // ================= prologue ================
    copyB(bB[0], (const uint4*)&g_wp[0][0][0][0], tid);   // B0 -> buf0
    copyB(bB[1], (const uint4*)&g_wp[1][0][0][0], tid);   // B1 -> buf1
    pf_load(pf, edg + arow);
    storeA(Ahi, Alo, pf, srow, sq, svalid);
    CP_WAIT1();                                           // B0 ready
    __syncthreads();

    // ---- chunk 0 (edge @ W0[0:128]) ----
    pf_load(pf, src + arow);                              // prefetch A1
    mma_chunk(acc, aHiL, aLoL, bHiL[0], bLoL[0]);
    __syncthreads();
    storeA(Ahi, Alo, pf, srow, sq, svalid);
    copyB(bB[0], (const uint4*)&g_wp[2][0][0][0], tid);   // B2 -> buf0
    CP_WAIT1();                                           // B1 ready
    __syncthreads();

    // ---- chunk 1 (src @ W0[128:256]) ----
    pf_load(pf, dst + arow);                              // prefetch A2
    mma_chunk(acc, aHiL, aLoL, bHiL[1], bLoL[1]);
    __syncthreads();
    storeA(Ahi, Alo, pf, srow, sq, svalid);
    copyB(bB[1], (const uint4*)&g_wp[3][0][0][0], tid);   // W1 -> buf1
    CP_WAIT1();                                           // B2 ready
    __syncthreads();

    // ---- chunk 2 (dest @ W0[256:384]) ----
    mma_chunk(acc, aHiL, aLoL, bHiL[0], bLoL[0]);
    __syncthreads();
    // epilogue 0: silu(acc + b0) -> A ; reset acc
    #pragma unroll
    for (int mt = 0; mt < 2; mt++)
        #pragma unroll
        for (int nt = 0; nt < 2; nt++) {
            int col = warp_n + 8 * nt + ec;
            float bb0 = __ldg(b0 + col), bb1 = __ldg(b0 + col + 1);
            int r0 = warp_m + 16 * mt + er0;
            int cp = ecp + 4 * nt;
            float h00 = silu_f(acc[mt][nt][0] + bb0);
            float h01 = silu_f(acc[mt][nt][1] + bb1);
            float h10 = silu_f(acc[mt][nt][2] + bb0);
            float h11 = silu_f(acc[mt][nt][3] + bb1);
            uint32_t lo0, lo1;
            uint32_t hi0 = pack_bf2(h00, h01, &lo0);
            uint32_t hi1 = pack_bf2(h10, h11, &lo1);
            Ahi[r0 * APAD + cp]       = hi0;
            Alo[r0 * APAD + cp]       = lo0;
            Ahi[(r0 + 8) * APAD + cp] = hi1;
            Alo[(r0 + 8) * APAD + cp] = lo1;
            acc[mt][nt][0] = 0.f; acc[mt][nt][1] = 0.f;
            acc[mt][nt][2] = 0.f; acc[mt][nt][3] = 0.f;
        }
    copyB(bB[0], (const uint4*)&g_wp[4][0][0][0], tid);   // W2 -> buf0
    CP_WAIT1();                                           // W1 ready
    __syncthreads();

    // ---- chunk 3 (h @ W1) ----
    mma_chunk(acc, aHiL, aLoL, bHiL[1], bLoL[1]);
    __syncthreads();
    // epilogue 1: silu(acc + b1) -> A ; reset acc
    #pragma unroll
    for (int mt = 0; mt < 2; mt++)
        #pragma unroll
        for (int nt = 0; nt < 2; nt++) {
            int col = warp_n + 8 * nt + ec;
            float bb0 = __ldg(b1 + col), bb1 = __ldg(b1 + col + 1);
            int r0 = warp_m + 16 * mt + er0;
            int cp = ecp + 4 * nt;
            float h00 = silu_f(acc[mt][nt][0] + bb0);
            float h01 = silu_f(acc[mt][nt][1] + bb1);
            float h10 = silu_f(acc[mt][nt][2] + bb0);
            float h11 = silu_f(acc[mt][nt][3] + bb1);
            uint32_t lo0, lo1;
            uint32_t hi0 = pack_bf2(h00, h01, &lo0);
            uint32_t hi1 = pack_bf2(h10, h11, &lo1);
            Ahi[r0 * APAD + cp]       = hi0;
            Alo[r0 * APAD + cp]       = lo0;
            Ahi[(r0 + 8) * APAD + cp] = hi1;
            Alo[(r0 + 8) * APAD + cp] = lo1;
            acc[mt][nt][0] = 0.f; acc[mt][nt][1] = 0.f;
            acc[mt][nt][2] = 0.f; acc[mt][nt][3] = 0.f;
        }
    CP_WAIT0();                                           // W2 ready
    __syncthreads();

    // ---- chunk 4 (h @ W2) ----
    mma_chunk(acc, aHiL, aLoL, bHiL[0], bLoL[0]);

    // final epilogue: acc + b2 -> out
    #pragma unroll
    for (int mt = 0; mt < 2; mt++)
        #pragma unroll
        for (int nt = 0; nt < 2; nt++) {
            int col = warp_n + 8 * nt + ec;
            float bb0 = __ldg(b2 + col), bb1 = __ldg(b2 + col + 1);
            int r0g = tile * TM + warp_m + 16 * mt + er0;
            if (r0g < E) {
                float2 v = { acc[mt][nt][0] + bb0, acc[mt][nt][1] + bb1 };
                *(float2*)(out + (size_t)r0g * DH + col) = v;
            }
            if (r0g + 8 < E) {
                float2 v = { acc[mt][nt][2] + bb0, acc[mt][nt][3] + bb1 };
                *(float2*)(out + (size_t)(r0g + 8) * DH + col) = v;
            }
        }
}

// ---------------- host ----------------
extern "C" void kernel_launch(void* const* d_in, const int* in_sizes, int n_in,
                              void* d_out, int out_size) {
    const float* src = (const float*)d_in[0];
    const float* dst = (const float*)d_in[1];
    const float* edg = (const float*)d_in[2];
    const float* W0  = (const float*)d_in[3];
    const float* b0  = (const float*)d_in[4];
    const float* W1  = (const float*)d_in[5];
    const float* b1  = (const float*)d_in[6];
    const float* W2  = (const float*)d_in[7];
    const float* b2  = (const float*)d_in[8];

    int E = in_sizes[0] / DH;
    int ntiles = (E + TM - 1) / TM;

    cudaFuncSetAttribute(mlp_kernel, cudaFuncAttributeMaxDynamicSharedMemorySize,
                         SMEM_TOTAL);

    prep_weights<<<(5 * 128 * 64 + 255) / 256, 256>>>(W0, W1, W2);
    mlp_kernel<<<ntiles, 512, SMEM_TOTAL>>>(src, dst, edg, b0, b1, b2,
                                            (float*)d_out, E);
}

// round 12
// speedup vs baseline: 1.0670x; 1.0670x over previous
#include <cuda_runtime.h>
#include <cuda_bf16.h>
#include <cstdint>

// EdgeModel fused 3-layer MLP via arch-agnostic mma.sync (bf16 3-term split).
// R11: one CTA = 512 threads = TWO 8-warp groups (R9's proven 32x32 warp-tile
// geometry, MMA:LDSM ratio 3), processing two 64-row tiles that SHARE all B
// loads (halves the dominant exposed cost: 348KB B copy per 64 rows), with
// double-buffered B via cp.async so the copy leaves the critical path.
// SMEM: A 2x34.8K + B 2x69.6K = 204KB -> 1 CTA/SM.

#define DH 128
#define TM 64
#define APAD 68
#define A_U32 (TM * APAD)             // 4352 (one hi or lo plane, one tile)
#define B_U32 (128 * APAD)            // 8704 (one hi or lo plane)
#define B_REG_U32 (2 * B_U32)         // hi+lo, one region
#define SMEM_U32 (4 * A_U32 + 2 * B_REG_U32)
#define SMEM_TOTAL (SMEM_U32 * 4)     // 208896

// weight images: 5 regions (W0 k-chunks 0..2, W1, W2) x {hi,lo} x [n][kp]
__device__ __align__(16) uint32_t g_wp[5][2][128][APAD];

// ---------------- helpers ----------------
__device__ __forceinline__ uint32_t smem_u32p(const void* p) {
    uint32_t a;
    asm("{ .reg .u64 t; cvta.to.shared.u64 t, %1; cvt.u32.u64 %0, t; }"
        : "=r"(a) : "l"(p));
    return a;
}

__device__ __forceinline__ uint32_t pack_bf2(float a0, float a1, uint32_t* lo_out) {
    __nv_bfloat16 h0 = __float2bfloat16(a0);
    __nv_bfloat16 h1 = __float2bfloat16(a1);
    __nv_bfloat16 l0 = __float2bfloat16(a0 - __bfloat162float(h0));
    __nv_bfloat16 l1 = __float2bfloat16(a1 - __bfloat162float(h1));
    *lo_out = (uint32_t)__bfloat16_as_ushort(l0) |
              ((uint32_t)__bfloat16_as_ushort(l1) << 16);
    return (uint32_t)__bfloat16_as_ushort(h0) |
           ((uint32_t)__bfloat16_as_ushort(h1) << 16);
}

__device__ __forceinline__ float silu_f(float x) {
    return x / (1.0f + __expf(-x));
}

#define LDSM4(r, addr)                                                         \
    asm volatile("ldmatrix.sync.aligned.m8n8.x4.shared.b16 {%0,%1,%2,%3}, [%4];" \
        : "=r"((r)[0]), "=r"((r)[1]), "=r"((r)[2]), "=r"((r)[3]) : "r"(addr))

#define MMA16816(c, a, b)                                                      \
    asm volatile("mma.sync.aligned.m16n8k16.row.col.f32.bf16.bf16.f32 "        \
        "{%0,%1,%2,%3}, {%4,%5,%6,%7}, {%8,%9}, {%0,%1,%2,%3};"                \
        : "+f"((c)[0]), "+f"((c)[1]), "+f"((c)[2]), "+f"((c)[3])               \
        : "r"((a)[0]), "r"((a)[1]), "r"((a)[2]), "r"((a)[3]),                  \
          "r"((b)[0]), "r"((b)[1]))

#define CP_ASYNC16(sm_addr, gptr)                                              \
    asm volatile("cp.async.cg.shared.global [%0], [%1], 16;"                   \
        :: "r"(sm_addr), "l"(gptr) : "memory")
#define CP_COMMIT()  asm volatile("cp.async.commit_group;" ::: "memory")
#define CP_WAIT1()   asm volatile("cp.async.wait_group 1;" ::: "memory")
#define CP_WAIT0()   asm volatile("cp.async.wait_group 0;" ::: "memory")

// ---------------- prep: pack weights into hi/lo ldmatrix-ready images -------
__global__ void prep_weights(const float* __restrict__ W0,
                             const float* __restrict__ W1,
                             const float* __restrict__ W2) {
    int i = blockIdx.x * blockDim.x + threadIdx.x;
    if (i >= 5 * 128 * 64) return;
    int r   = i >> 13;
    int rem = i & 8191;
    int n   = rem >> 6;
    int kp  = rem & 63;
    const float* W = (r < 3) ? W0 : (r == 3) ? W1 : W2;
    int k0 = ((r < 3) ? r * 128 : 0) + 2 * kp;
    float v0 = W[(size_t)k0 * DH + n];
    float v1 = W[(size_t)(k0 + 1) * DH + n];
    uint32_t lo;
    uint32_t hi = pack_bf2(v0, v1, &lo);
    g_wp[r][0][n][kp] = hi;
    g_wp[r][1][n][kp] = lo;
}

// ---------------- device pieces ----------------
__device__ __forceinline__ void copyB(uint32_t dstb, const uint4* s, int tid) {
    #pragma unroll 1
    for (int i = tid; i < B_REG_U32 / 4; i += 512)
        CP_ASYNC16(dstb + i * 16, s + i);
    CP_COMMIT();
}

// stage one 128-row (both tiles) fp32 chunk -> bf16 hi/lo SMEM planes
__device__ __forceinline__ void stageA(uint32_t* sm, const float* xp,
                                       int srow, int sq, int grow_s, bool sv) {
    uint32_t* Ahi = sm + (srow >> 6) * (2 * A_U32);
    uint32_t* Alo = Ahi + A_U32;
    int lrow = srow & 63;
    const float4* p = (const float4*)(xp + (size_t)grow_s * DH + sq * 32);
    #pragma unroll
    for (int q = 0; q < 8; q++) {
        float4 v = sv ? p[q] : make_float4(0.f, 0.f, 0.f, 0.f);
        uint32_t lo0, lo1;
        uint32_t h0 = pack_bf2(v.x, v.y, &lo0);
        uint32_t h1 = pack_bf2(v.z, v.w, &lo1);
        int kp = sq * 16 + 2 * q;
        Ahi[lrow * APAD + kp]     = h0;
        Ahi[lrow * APAD + kp + 1] = h1;
        Alo[lrow * APAD + kp]     = lo0;
        Alo[lrow * APAD + kp + 1] = lo1;
    }
}

// R9's verified ratio-3 MMA chunk: warp tile 32x32, acc[2][4][4]
__device__ __forceinline__ void mma_chunk(float acc[2][4][4],
                                          uint32_t aHiL, uint32_t aLoL,
                                          uint32_t bHiL, uint32_t bLoL) {
    #pragma unroll 2
    for (int ks = 0; ks < 8; ks++) {
        uint32_t ah[2][4], al[2][4], bh[2][4], bl[2][4];
        #pragma unroll
        for (int mt = 0; mt < 2; mt++) {
            uint32_t off = mt * (16 * APAD * 4) + ks * 32;
            LDSM4(ah[mt], aHiL + off);
            LDSM4(al[mt], aLoL + off);
        }
        #pragma unroll
        for (int jj = 0; jj < 2; jj++) {
            uint32_t off = jj * (16 * APAD * 4) + ks * 32;
            LDSM4(bh[jj], bHiL + off);
            LDSM4(bl[jj], bLoL + off);
        }
        #pragma unroll
        for (int mt = 0; mt < 2; mt++)
            #pragma unroll
            for (int nt = 0; nt < 4; nt++) {
                const uint32_t* pbh = &bh[nt >> 1][(nt & 1) * 2];
                const uint32_t* pbl = &bl[nt >> 1][(nt & 1) * 2];
                MMA16816(acc[mt][nt], ah[mt], pbh);   // Ah*Bh
                MMA16816(acc[mt][nt], al[mt], pbh);   // Al*Bh
                MMA16816(acc[mt][nt], ah[mt], pbl);   // Ah*Bl
            }
    }
}

// ---------------- fused MLP kernel ----------------
__global__ void __launch_bounds__(512)
mlp_kernel(const float* __restrict__ src, const float* __restrict__ dst,
           const float* __restrict__ edg,
           const float* __restrict__ b0, const float* __restrict__ b1,
           const float* __restrict__ b2,
           float* __restrict__ out, int E)
{
    extern __shared__ uint32_t sm[];
    // layout (u32): A0hi A0lo A1hi A1lo | B buf0 (hi,lo) | B buf1 (hi,lo)
    const uint32_t smb = smem_u32p(sm);
    const uint32_t bB[2] = { smb + 4 * A_U32 * 4,
                             smb + 4 * A_U32 * 4 + B_REG_U32 * 4 };

    const int tid = threadIdx.x;
    const int l = tid & 31, w = tid >> 5;
    const int g  = w >> 3;            // tile group 0/1
    const int wg = w & 7;             // warp within group (R9 geometry)
    const int warp_m = (wg & 1) * 32;
    const int warp_n = (wg >> 1) * 32;
    const int stile = blockIdx.x;     // super-tile: 128 rows

    // ldmatrix per-lane offsets (verified mapping, R8/R9)
    const int laneA_r = (l & 7) + ((l >> 3) & 1) * 8;
    const int laneA_k = ((l >> 4) & 1) * 4;
    const int laneB_r = (l & 7) + ((l >> 4) & 1) * 8;
    const int laneB_k = ((l >> 3) & 1) * 4;
    const uint32_t aHiL = smb + g * (2 * A_U32 * 4) +
                          ((warp_m + laneA_r) * APAD + laneA_k) * 4;
    const uint32_t aLoL = aHiL + A_U32 * 4;
    const uint32_t boff = ((warp_n + laneB_r) * APAD + laneB_k) * 4;
    const uint32_t bHiL[2] = { bB[0] + boff, bB[1] + boff };
    const uint32_t bLoL[2] = { bB[0] + B_U32 * 4 + boff,
                               bB[1] + B_U32 * 4 + boff };

    float acc[2][4][4];
    #pragma unroll
    for (int mt = 0; mt < 2; mt++)
        #pragma unroll
        for (int nt = 0; nt < 4; nt++)
            #pragma unroll
            for (int q = 0; q < 4; q++) acc[mt][nt][q] = 0.f;

    // A staging map: 512 thr -> (row 0..127 of super-tile, 32-col quarter)
    const int srow = tid >> 2, sq = tid & 3;
    const int grow_s = stile * 128 + srow;
    const bool svalid = grow_s < E;

    // epilogue lane constants (R9 formulas)
    const int er0 = (l >> 2);
    const int ec  = (l & 3) * 2;
    const int ecp = (warp_n >> 1) + (l & 3);
    // A-write pointers for this warp's tile group
    uint32_t* myAhi = sm + g * (2 * A_U32);
    uint32_t* myAlo = myAhi + A_U32;

    // ================= prologue ================
    copyB(bB[0], (const uint4*)&g_wp[0][0][0][0], tid);   // region0 -> buf0
    copyB(bB[1], (const uint4*)&g_wp[1][0][0][0], tid);   // region1 -> buf1
    stageA(sm, edg, srow, sq, grow_s, svalid);
    CP_WAIT1();                                           // buf0 ready
    __syncthreads();

    // ---- chunk 0 (edge @ W0[0:128]) ----
    mma_chunk(acc, aHiL, aLoL, bHiL[0], bLoL[0]);
    __syncthreads();
    stageA(sm, src, srow, sq, grow_s, svalid);
    copyB(bB[0], (const uint4*)&g_wp[2][0][0][0], tid);   // region2 -> buf0
    CP_WAIT1();                                           // buf1 ready
    __syncthreads();

    // ---- chunk 1 (src @ W0[128:256]) ----
    mma_chunk(acc, aHiL, aLoL, bHiL[1], bLoL[1]);
    __syncthreads();
    stageA(sm, dst, srow, sq, grow_s, svalid);
    copyB(bB[1], (const uint4*)&g_wp[3][0][0][0], tid);   // W1 -> buf1
    CP_WAIT1();                                           // buf0 ready
    __syncthreads();

    // ---- chunk 2 (dest @ W0[256:384]) ----
    mma_chunk(acc, aHiL, aLoL, bHiL[0], bLoL[0]);
    __syncthreads();
    // epilogue 0: silu(acc + b0) -> A ; reset acc
    #pragma unroll
    for (int mt = 0; mt < 2; mt++)
        #pragma unroll
        for (int nt = 0; nt < 4; nt++) {
            int col = warp_n + 8 * nt + ec;
            float bb0 = __ldg(b0 + col), bb1 = __ldg(b0 + col + 1);
            int r0 = warp_m + 16 * mt + er0;
            int cp = ecp + 4 * nt;
            float h00 = silu_f(acc[mt][nt][0] + bb0);
            float h01 = silu_f(acc[mt][nt][1] + bb1);
            float h10 = silu_f(acc[mt][nt][2] + bb0);
            float h11 = silu_f(acc[mt][nt][3] + bb1);
            uint32_t lo0, lo1;
            uint32_t hi0 = pack_bf2(h00, h01, &lo0);
            uint32_t hi1 = pack_bf2(h10, h11, &lo1);
            myAhi[r0 * APAD + cp]       = hi0;
            myAlo[r0 * APAD + cp]       = lo0;
            myAhi[(r0 + 8) * APAD + cp] = hi1;
            myAlo[(r0 + 8) * APAD + cp] = lo1;
            acc[mt][nt][0] = 0.f; acc[mt][nt][1] = 0.f;
            acc[mt][nt][2] = 0.f; acc[mt][nt][3] = 0.f;
        }
    copyB(bB[0], (const uint4*)&g_wp[4][0][0][0], tid);   // W2 -> buf0
    CP_WAIT1();                                           // buf1 (W1) ready
    __syncthreads();

    // ---- chunk 3 (h @ W1) ----
    mma_chunk(acc, aHiL, aLoL, bHiL[1], bLoL[1]);
    __syncthreads();
    // epilogue 1: silu(acc + b1) -> A ; reset acc
    #pragma unroll
    for (int mt = 0; mt < 2; mt++)
        #pragma unroll
        for (int nt = 0; nt < 4; nt++) {
            int col = warp_n + 8 * nt + ec;
            float bb0 = __ldg(b1 + col), bb1 = __ldg(b1 + col + 1);
            int r0 = warp_m + 16 * mt + er0;
            int cp = ecp + 4 * nt;
            float h00 = silu_f(acc[mt][nt][0] + bb0);
            float h01 = silu_f(acc[mt][nt][1] + bb1);
            float h10 = silu_f(acc[mt][nt][2] + bb0);
            float h11 = silu_f(acc[mt][nt][3] + bb1);
            uint32_t lo0, lo1;
            uint32_t hi0 = pack_bf2(h00, h01, &lo0);
            uint32_t hi1 = pack_bf2(h10, h11, &lo1);
            myAhi[r0 * APAD + cp]       = hi0;
            myAlo[r0 * APAD + cp]       = lo0;
            myAhi[(r0 + 8) * APAD + cp] = hi1;
            myAlo[(r0 + 8) * APAD + cp] = lo1;
            acc[mt][nt][0] = 0.f; acc[mt][nt][1] = 0.f;
            acc[mt][nt][2] = 0.f; acc[mt][nt][3] = 0.f;
        }
    CP_WAIT0();                                           // buf0 (W2) ready
    __syncthreads();

    // ---- chunk 4 (h @ W2) ----
    mma_chunk(acc, aHiL, aLoL, bHiL[0], bLoL[0]);

    // final epilogue: acc + b2 -> out
    #pragma unroll
    for (int mt = 0; mt < 2; mt++)
        #pragma unroll
        for (int nt = 0; nt < 4; nt++) {
            int col = warp_n + 8 * nt + ec;
            float bb0 = __ldg(b2 + col), bb1 = __ldg(b2 + col + 1);
            int r0g = stile * 128 + g * 64 + warp_m + 16 * mt + er0;
            if (r0g < E) {
                float2 v = { acc[mt][nt][0] + bb0, acc[mt][nt][1] + bb1 };
                *(float2*)(out + (size_t)r0g * DH + col) = v;
            }
            if (r0g + 8 < E) {
                float2 v = { acc[mt][nt][2] + bb0, acc[mt][nt][3] + bb1 };
                *(float2*)(out + (size_t)(r0g + 8) * DH + col) = v;
            }
        }
}

// ---------------- host ----------------
extern "C" void kernel_launch(void* const* d_in, const int* in_sizes, int n_in,
                              void* d_out, int out_size) {
    const float* src = (const float*)d_in[0];
    const float* dst = (const float*)d_in[1];
    const float* edg = (const float*)d_in[2];
    const float* W0  = (const float*)d_in[3];
    const float* b0  = (const float*)d_in[4];
    const float* W1  = (const float*)d_in[5];
    const float* b1  = (const float*)d_in[6];
    const float* W2  = (const float*)d_in[7];
    const float* b2  = (const float*)d_in[8];

    int E = in_sizes[0] / DH;
    int nsuper = (E + 127) / 128;

    cudaFuncSetAttribute(mlp_kernel, cudaFuncAttributeMaxDynamicSharedMemorySize,
                         SMEM_TOTAL);

    prep_weights<<<(5 * 128 * 64 + 255) / 256, 256>>>(W0, W1, W2);
    mlp_kernel<<<nsuper, 512, SMEM_TOTAL>>>(src, dst, edg, b0, b1, b2,
                                            (float*)d_out, E);
}

// round 13
// speedup vs baseline: 1.3272x; 1.2439x over previous
#include <cuda_runtime.h>
#include <cuda_bf16.h>
#include <cstdint>

// EdgeModel fused 3-layer MLP via arch-agnostic mma.sync (bf16 3-term split).
// R12: B never touches SMEM. Weights are pre-packed into a fragment-ordered
// global image g_wf[region][plane][ks][n8][lane][2] (warp reads = coalesced
// 256B lines, L2/L1-resident, 320KB total), loaded with __ldg(uint2) straight
// into mma operands. SMEM/CTA = A only (34.8KB) -> 3 CTAs/SM (24 warps) to
// fill the inter-phase latency stalls that capped R9-R11 at 42-46% tensor.
// Per-CTA geometry = R9's verified 8-warp 32x32 warp tiles, ratio-3 MMA.

#define DH 128
#define APAD 68
#define A_U32 (64 * APAD)             // one plane (hi or lo), 64 rows

// fragment-ordered weight image:
// [region 0..4][plane hi/lo][ks 0..7][n8 0..15][lane 0..31][j 0..1]
// value(j) = pack_bf16(W[k][n], W[k+1][n]), k = ks*16 + 2*(l&3) + j*8,
//            n = n8*8 + (l>>2); region 0..2 = W0 k-chunks, 3 = W1, 4 = W2.
__device__ __align__(16) uint32_t g_wf[5][2][8][16][32][2];

#define WF_PLANE 8192                  // u32 stride between hi and lo planes

// ---------------- helpers ----------------
__device__ __forceinline__ uint32_t smem_u32p(const void* p) {
    uint32_t a;
    asm("{ .reg .u64 t; cvta.to.shared.u64 t, %1; cvt.u32.u64 %0, t; }"
        : "=r"(a) : "l"(p));
    return a;
}

__device__ __forceinline__ uint32_t pack_bf2(float a0, float a1, uint32_t* lo_out) {
    __nv_bfloat16 h0 = __float2bfloat16(a0);
    __nv_bfloat16 h1 = __float2bfloat16(a1);
    __nv_bfloat16 l0 = __float2bfloat16(a0 - __bfloat162float(h0));
    __nv_bfloat16 l1 = __float2bfloat16(a1 - __bfloat162float(h1));
    *lo_out = (uint32_t)__bfloat16_as_ushort(l0) |
              ((uint32_t)__bfloat16_as_ushort(l1) << 16);
    return (uint32_t)__bfloat16_as_ushort(h0) |
           ((uint32_t)__bfloat16_as_ushort(h1) << 16);
}

__device__ __forceinline__ float silu_f(float x) {
    return x / (1.0f + __expf(-x));
}

#define LDSM4(r, addr)                                                         \
    asm volatile("ldmatrix.sync.aligned.m8n8.x4.shared.b16 {%0,%1,%2,%3}, [%4];" \
        : "=r"((r)[0]), "=r"((r)[1]), "=r"((r)[2]), "=r"((r)[3]) : "r"(addr))

#define MMA16816(c, a, b0, b1)                                                 \
    asm volatile("mma.sync.aligned.m16n8k16.row.col.f32.bf16.bf16.f32 "        \
        "{%0,%1,%2,%3}, {%4,%5,%6,%7}, {%8,%9}, {%0,%1,%2,%3};"                \
        : "+f"((c)[0]), "+f"((c)[1]), "+f"((c)[2]), "+f"((c)[3])               \
        : "r"((a)[0]), "r"((a)[1]), "r"((a)[2]), "r"((a)[3]),                  \
          "r"(b0), "r"(b1))

// ---------------- prep: pack weights into fragment-ordered hi/lo image ------
__global__ void prep_weights(const float* __restrict__ W0,
                             const float* __restrict__ W1,
                             const float* __restrict__ W2) {
    int i = blockIdx.x * blockDim.x + threadIdx.x;
    if (i >= 5 * 2 * 8 * 16 * 32 * 2) return;     // 81920
    int j  = i & 1;
    int l  = (i >> 1) & 31;
    int n8 = (i >> 6) & 15;
    int ks = (i >> 10) & 7;
    int p  = (i >> 13) & 1;
    int r  = i >> 14;
    const float* W = (r < 3) ? W0 : (r == 3) ? W1 : W2;
    int n  = n8 * 8 + (l >> 2);
    int k0 = ((r < 3) ? r * 128 : 0) + ks * 16 + 2 * (l & 3) + j * 8;
    float v0 = W[(size_t)k0 * DH + n];
    float v1 = W[(size_t)(k0 + 1) * DH + n];
    uint32_t lo;
    uint32_t hi = pack_bf2(v0, v1, &lo);
    g_wf[r][p][ks][n8][l][j] = p ? lo : hi;
}

// ---------------- device pieces ----------------
// stage one 64-row fp32 chunk -> bf16 hi/lo SMEM planes (R9-verified layout)
__device__ __forceinline__ void stageA(uint32_t* Ahi, uint32_t* Alo,
                                       const float* xp, int srow, int sq,
                                       int grow_s, bool sv) {
    const float4* p = (const float4*)(xp + (size_t)grow_s * DH + sq * 32);
    #pragma unroll
    for (int q = 0; q < 8; q++) {
        float4 v = sv ? p[q] : make_float4(0.f, 0.f, 0.f, 0.f);
        uint32_t lo0, lo1;
        uint32_t h0 = pack_bf2(v.x, v.y, &lo0);
        uint32_t h1 = pack_bf2(v.z, v.w, &lo1);
        int kp = sq * 16 + 2 * q;
        Ahi[srow * APAD + kp]     = h0;
        Ahi[srow * APAD + kp + 1] = h1;
        Alo[srow * APAD + kp]     = lo0;
        Alo[srow * APAD + kp + 1] = lo1;
    }
}

// ratio-3 MMA chunk; A from SMEM via ldmatrix, B fragments via __ldg
__device__ __forceinline__ void mma_chunk(float acc[2][4][4],
                                          uint32_t aHiL, uint32_t aLoL,
                                          const uint32_t* __restrict__ wf,
                                          int n8base, int l) {
    #pragma unroll 2
    for (int ks = 0; ks < 8; ks++) {
        uint32_t ah[2][4], al[2][4];
        #pragma unroll
        for (int mt = 0; mt < 2; mt++) {
            uint32_t off = mt * (16 * APAD * 4) + ks * 32;
            LDSM4(ah[mt], aHiL + off);
            LDSM4(al[mt], aLoL + off);
        }
        uint2 bh[4], bl[4];
        const uint32_t* base = wf + ks * 1024 + n8base * 64 + l * 2;
        #pragma unroll
        for (int nt = 0; nt < 4; nt++) {
            bh[nt] = __ldg((const uint2*)(base + nt * 64));
            bl[nt] = __ldg((const uint2*)(base + nt * 64 + WF_PLANE));
        }
        #pragma unroll
        for (int mt = 0; mt < 2; mt++)
            #pragma unroll
            for (int nt = 0; nt < 4; nt++) {
                MMA16816(acc[mt][nt], ah[mt], bh[nt].x, bh[nt].y);  // Ah*Bh
                MMA16816(acc[mt][nt], al[mt], bh[nt].x, bh[nt].y);  // Al*Bh
                MMA16816(acc[mt][nt], ah[mt], bl[nt].x, bl[nt].y);  // Ah*Bl
            }
    }
}

// ---------------- fused MLP kernel ----------------
__global__ void __launch_bounds__(256, 3)
mlp_kernel(const float* __restrict__ src, const float* __restrict__ dst,
           const float* __restrict__ edg,
           const float* __restrict__ b0, const float* __restrict__ b1,
           const float* __restrict__ b2,
           float* __restrict__ out, int E)
{
    __shared__ __align__(16) uint32_t sA[2 * A_U32];   // 34816 B: Ahi | Alo
    uint32_t* Ahi = sA;
    uint32_t* Alo = sA + A_U32;

    const int tid = threadIdx.x;
    const int l = tid & 31, w = tid >> 5;
    const int warp_m = (w & 1) * 32;
    const int warp_n = (w >> 1) * 32;
    const int n8base = (w >> 1) * 4;
    const int tile = blockIdx.x;

    // ldmatrix A per-lane offsets (verified mapping, R8/R9)
    const int laneA_r = (l & 7) + ((l >> 3) & 1) * 8;
    const int laneA_k = ((l >> 4) & 1) * 4;
    const uint32_t smb  = smem_u32p(sA);
    const uint32_t aHiL = smb + ((warp_m + laneA_r) * APAD + laneA_k) * 4;
    const uint32_t aLoL = aHiL + A_U32 * 4;

    float acc[2][4][4];
    #pragma unroll
    for (int mt = 0; mt < 2; mt++)
        #pragma unroll
        for (int nt = 0; nt < 4; nt++)
            #pragma unroll
            for (int q = 0; q < 4; q++) acc[mt][nt][q] = 0.f;

    // A staging map: 256 thr -> (row 0..63, 32-col quarter)
    const int srow = tid >> 2, sq = tid & 3;
    const int grow_s = tile * 64 + srow;
    const bool svalid = grow_s < E;

    // epilogue lane constants (R9 formulas)
    const int er0 = (l >> 2);
    const int ec  = (l & 3) * 2;
    const int ecp = (warp_n >> 1) + (l & 3);

    // ================= layer 0: 3 k-chunks (edge, src, dest) ================
    #pragma unroll 1
    for (int c = 0; c < 3; c++) {
        const float* xp = (c == 0) ? edg : (c == 1) ? src : dst;
        stageA(Ahi, Alo, xp, srow, sq, grow_s, svalid);
        __syncthreads();
        mma_chunk(acc, aHiL, aLoL, &g_wf[c][0][0][0][0][0], n8base, l);
        __syncthreads();
    }

    // =============== layers 1 & 2 ===============
    #pragma unroll 1
    for (int layer = 1; layer <= 2; layer++) {
        const float* bias = (layer == 1) ? b0 : b1;   // bias of the PREVIOUS gemm
        // epilogue: silu(acc + bias) -> A ; reset acc
        #pragma unroll
        for (int mt = 0; mt < 2; mt++)
            #pragma unroll
            for (int nt = 0; nt < 4; nt++) {
                int col = warp_n + 8 * nt + ec;
                float bb0 = __ldg(bias + col), bb1 = __ldg(bias + col + 1);
                int r0 = warp_m + 16 * mt + er0;
                int cp = ecp + 4 * nt;
                float h00 = silu_f(acc[mt][nt][0] + bb0);
                float h01 = silu_f(acc[mt][nt][1] + bb1);
                float h10 = silu_f(acc[mt][nt][2] + bb0);
                float h11 = silu_f(acc[mt][nt][3] + bb1);
                uint32_t lo0, lo1;
                uint32_t hi0 = pack_bf2(h00, h01, &lo0);
                uint32_t hi1 = pack_bf2(h10, h11, &lo1);
                Ahi[r0 * APAD + cp]       = hi0;
                Alo[r0 * APAD + cp]       = lo0;
                Ahi[(r0 + 8) * APAD + cp] = hi1;
                Alo[(r0 + 8) * APAD + cp] = lo1;
                acc[mt][nt][0] = 0.f; acc[mt][nt][1] = 0.f;
                acc[mt][nt][2] = 0.f; acc[mt][nt][3] = 0.f;
            }
        __syncthreads();
        mma_chunk(acc, aHiL, aLoL, &g_wf[layer + 2][0][0][0][0][0], n8base, l);
        __syncthreads();
    }

    // =============== final epilogue: acc + b2 -> out ===============
    #pragma unroll
    for (int mt = 0; mt < 2; mt++)
        #pragma unroll
        for (int nt = 0; nt < 4; nt++) {
            int col = warp_n + 8 * nt + ec;
            float bb0 = __ldg(b2 + col), bb1 = __ldg(b2 + col + 1);
            int r0g = tile * 64 + warp_m + 16 * mt + er0;
            if (r0g < E) {
                float2 v = { acc[mt][nt][0] + bb0, acc[mt][nt][1] + bb1 };
                *(float2*)(out + (size_t)r0g * DH + col) = v;
            }
            if (r0g + 8 < E) {
                float2 v = { acc[mt][nt][2] + bb0, acc[mt][nt][3] + bb1 };
                *(float2*)(out + (size_t)(r0g + 8) * DH + col) = v;
            }
        }
}

// ---------------- host ----------------
extern "C" void kernel_launch(void* const* d_in, const int* in_sizes, int n_in,
                              void* d_out, int out_size) {
    const float* src = (const float*)d_in[0];
    const float* dst = (const float*)d_in[1];
    const float* edg = (const float*)d_in[2];
    const float* W0  = (const float*)d_in[3];
    const float* b0  = (const float*)d_in[4];
    const float* W1  = (const float*)d_in[5];
    const float* b1  = (const float*)d_in[6];
    const float* W2  = (const float*)d_in[7];
    const float* b2  = (const float*)d_in[8];

    int E = in_sizes[0] / DH;
    int ntiles = (E + 63) / 64;

    prep_weights<<<(81920 + 255) / 256, 256>>>(W0, W1, W2);
    mlp_kernel<<<ntiles, 256>>>(src, dst, edg, b0, b1, b2, (float*)d_out, E);
}

// round 15
// speedup vs baseline: 2.1167x; 1.5949x over previous
#include <cuda_runtime.h>
#include <cuda_fp16.h>
#include <cstdint>

// EdgeModel fused 3-layer MLP via arch-agnostic mma.sync.
// R13/R14: SINGLE-PASS FP16 (f32 accumulate). Error analysis: harness rel_err
// metric matched the rms prediction for bf16-3-term (8.3e-6 vs 7.6e-6), so
// fp16 single-pass should land ~3-6e-4 < 1e-3. Cost drops 3x in MMA instrs
// and 2x in A/B L1 bytes (L1tex was the R12 co-binding pipe at 68.6%).
// smem 17.4KB, low regs -> 4 CTAs/SM (32 warps) for latency masking.
// Geometry/fragment maps identical to verified R12 (8 warps, 32x32 tiles).
// (Resubmit: R13 bench died at the broker, not in the kernel.)

#define DH 128
#define APAD 68
#define A_U32 (64 * APAD)             // 4352 u32 = 17408 B (single fp16 plane)

// fragment-ordered weight image (single fp16 plane):
// [region 0..4][ks 0..7][n8 0..15][lane 0..31][j 0..1]
// value(j) = half2(W[k][n], W[k+1][n]), k = ks*16 + 2*(l&3) + j*8,
//            n = n8*8 + (l>>2); regions 0..2 = W0 k-chunks, 3 = W1, 4 = W2.
__device__ __align__(16) uint32_t g_wf[5][8][16][32][2];
#define WF_REGION (8 * 16 * 32 * 2)   // 8192 u32 per region

// ---------------- helpers ----------------
__device__ __forceinline__ uint32_t smem_u32p(const void* p) {
    uint32_t a;
    asm("{ .reg .u64 t; cvta.to.shared.u64 t, %1; cvt.u32.u64 %0, t; }"
        : "=r"(a) : "l"(p));
    return a;
}

__device__ __forceinline__ uint32_t pack_h2(float a0, float a1) {
    __half2 h = __floats2half2_rn(a0, a1);
    return *(uint32_t*)&h;
}

__device__ __forceinline__ float silu_f(float x) {
    return x / (1.0f + __expf(-x));
}

#define LDSM4(r, addr)                                                         \
    asm volatile("ldmatrix.sync.aligned.m8n8.x4.shared.b16 {%0,%1,%2,%3}, [%4];" \
        : "=r"((r)[0]), "=r"((r)[1]), "=r"((r)[2]), "=r"((r)[3]) : "r"(addr))

#define MMA16816(c, a, b0, b1)                                                 \
    asm volatile("mma.sync.aligned.m16n8k16.row.col.f32.f16.f16.f32 "          \
        "{%0,%1,%2,%3}, {%4,%5,%6,%7}, {%8,%9}, {%0,%1,%2,%3};"                \
        : "+f"((c)[0]), "+f"((c)[1]), "+f"((c)[2]), "+f"((c)[3])               \
        : "r"((a)[0]), "r"((a)[1]), "r"((a)[2]), "r"((a)[3]),                  \
          "r"(b0), "r"(b1))

// ---------------- prep: pack weights into fragment-ordered fp16 image -------
__global__ void prep_weights(const float* __restrict__ W0,
                             const float* __restrict__ W1,
                             const float* __restrict__ W2) {
    int i = blockIdx.x * blockDim.x + threadIdx.x;
    if (i >= 5 * 8 * 16 * 32 * 2) return;          // 40960
    int j  = i & 1;
    int l  = (i >> 1) & 31;
    int n8 = (i >> 6) & 15;
    int ks = (i >> 10) & 7;
    int r  = i >> 13;
    const float* W = (r < 3) ? W0 : (r == 3) ? W1 : W2;
    int n  = n8 * 8 + (l >> 2);
    int k0 = ((r < 3) ? r * 128 : 0) + ks * 16 + 2 * (l & 3) + j * 8;
    float v0 = W[(size_t)k0 * DH + n];
    float v1 = W[(size_t)(k0 + 1) * DH + n];
    g_wf[r][ks][n8][l][j] = pack_h2(v0, v1);
}

// ---------------- device pieces ----------------
// stage one 64-row fp32 chunk -> fp16 SMEM plane (R12-verified layout)
__device__ __forceinline__ void stageA(uint32_t* A, const float* xp,
                                       int srow, int sq, int grow_s, bool sv) {
    const float4* p = (const float4*)(xp + (size_t)grow_s * DH + sq * 32);
    #pragma unroll
    for (int q = 0; q < 8; q++) {
        float4 v = sv ? p[q] : make_float4(0.f, 0.f, 0.f, 0.f);
        int kp = sq * 16 + 2 * q;
        A[srow * APAD + kp]     = pack_h2(v.x, v.y);
        A[srow * APAD + kp + 1] = pack_h2(v.z, v.w);
    }
}

// single-pass MMA chunk; A from SMEM via ldmatrix, B fragments via __ldg
__device__ __forceinline__ void mma_chunk(float acc[2][4][4], uint32_t aL,
                                          const uint32_t* __restrict__ wf,
                                          int n8base, int l) {
    #pragma unroll 2
    for (int ks = 0; ks < 8; ks++) {
        // B first (global latency overlaps the A ldsm latency)
        uint2 bh[4];
        const uint32_t* base = wf + ks * 1024 + n8base * 64 + l * 2;
        #pragma unroll
        for (int nt = 0; nt < 4; nt++)
            bh[nt] = __ldg((const uint2*)(base + nt * 64));
        uint32_t ah[2][4];
        #pragma unroll
        for (int mt = 0; mt < 2; mt++)
            LDSM4(ah[mt], aL + mt * (16 * APAD * 4) + ks * 32);
        #pragma unroll
        for (int mt = 0; mt < 2; mt++)
            #pragma unroll
            for (int nt = 0; nt < 4; nt++)
                MMA16816(acc[mt][nt], ah[mt], bh[nt].x, bh[nt].y);
    }
}

// ---------------- fused MLP kernel ----------------
__global__ void __launch_bounds__(256, 4)
mlp_kernel(const float* __restrict__ src, const float* __restrict__ dst,
           const float* __restrict__ edg,
           const float* __restrict__ b0, const float* __restrict__ b1,
           const float* __restrict__ b2,
           float* __restrict__ out, int E)
{
    __shared__ __align__(16) uint32_t sA[A_U32];   // 17408 B

    const int tid = threadIdx.x;
    const int l = tid & 31, w = tid >> 5;
    const int warp_m = (w & 1) * 32;
    const int warp_n = (w >> 1) * 32;
    const int n8base = (w >> 1) * 4;
    const int tile = blockIdx.x;

    // ldmatrix A per-lane offsets (verified mapping, R8/R9/R12)
    const int laneA_r = (l & 7) + ((l >> 3) & 1) * 8;
    const int laneA_k = ((l >> 4) & 1) * 4;
    const uint32_t aL = smem_u32p(sA) +
                        ((warp_m + laneA_r) * APAD + laneA_k) * 4;

    float acc[2][4][4];
    #pragma unroll
    for (int mt = 0; mt < 2; mt++)
        #pragma unroll
        for (int nt = 0; nt < 4; nt++)
            #pragma unroll
            for (int q = 0; q < 4; q++) acc[mt][nt][q] = 0.f;

    // A staging map: 256 thr -> (row 0..63, 32-col quarter)
    const int srow = tid >> 2, sq = tid & 3;
    const int grow_s = tile * 64 + srow;
    const bool svalid = grow_s < E;

    // epilogue lane constants (R9/R12 formulas)
    const int er0 = (l >> 2);
    const int ec  = (l & 3) * 2;
    const int ecp = (warp_n >> 1) + (l & 3);

    // ================= layer 0: 3 k-chunks (edge, src, dest) ================
    #pragma unroll 1
    for (int c = 0; c < 3; c++) {
        const float* xp = (c == 0) ? edg : (c == 1) ? src : dst;
        stageA(sA, xp, srow, sq, grow_s, svalid);
        __syncthreads();
        mma_chunk(acc, aL, &g_wf[c][0][0][0][0], n8base, l);
        __syncthreads();
    }

    // =============== layers 1 & 2 ===============
    #pragma unroll 1
    for (int layer = 1; layer <= 2; layer++) {
        const float* bias = (layer == 1) ? b0 : b1;   // bias of the PREVIOUS gemm
        // epilogue: silu(acc + bias) -> A ; reset acc
        #pragma unroll
        for (int mt = 0; mt < 2; mt++)
            #pragma unroll
            for (int nt = 0; nt < 4; nt++) {
                int col = warp_n + 8 * nt + ec;
                float bb0 = __ldg(bias + col), bb1 = __ldg(bias + col + 1);
                int r0 = warp_m + 16 * mt + er0;
                int cp = ecp + 4 * nt;
                float h00 = silu_f(acc[mt][nt][0] + bb0);
                float h01 = silu_f(acc[mt][nt][1] + bb1);
                float h10 = silu_f(acc[mt][nt][2] + bb0);
                float h11 = silu_f(acc[mt][nt][3] + bb1);
                sA[r0 * APAD + cp]       = pack_h2(h00, h01);
                sA[(r0 + 8) * APAD + cp] = pack_h2(h10, h11);
                acc[mt][nt][0] = 0.f; acc[mt][nt][1] = 0.f;
                acc[mt][nt][2] = 0.f; acc[mt][nt][3] = 0.f;
            }
        __syncthreads();
        mma_chunk(acc, aL, &g_wf[layer + 2][0][0][0][0], n8base, l);
        __syncthreads();
    }

    // =============== final epilogue: acc + b2 -> out ===============
    #pragma unroll
    for (int mt = 0; mt < 2; mt++)
        #pragma unroll
        for (int nt = 0; nt < 4; nt++) {
            int col = warp_n + 8 * nt + ec;
            float bb0 = __ldg(b2 + col), bb1 = __ldg(b2 + col + 1);
            int r0g = tile * 64 + warp_m + 16 * mt + er0;
            if (r0g < E) {
                float2 v = { acc[mt][nt][0] + bb0, acc[mt][nt][1] + bb1 };
                *(float2*)(out + (size_t)r0g * DH + col) = v;
            }
            if (r0g + 8 < E) {
                float2 v = { acc[mt][nt][2] + bb0, acc[mt][nt][3] + bb1 };
                *(float2*)(out + (size_t)(r0g + 8) * DH + col) = v;
            }
        }
}

// ---------------- host ----------------
extern "C" void kernel_launch(void* const* d_in, const int* in_sizes, int n_in,
                              void* d_out, int out_size) {
    const float* src = (const float*)d_in[0];
    const float* dst = (const float*)d_in[1];
    const float* edg = (const float*)d_in[2];
    const float* W0  = (const float*)d_in[3];
    const float* b0  = (const float*)d_in[4];
    const float* W1  = (const float*)d_in[5];
    const float* b1  = (const float*)d_in[6];
    const float* W2  = (const float*)d_in[7];
    const float* b2  = (const float*)d_in[8];

    int E = in_sizes[0] / DH;
    int ntiles = (E + 63) / 64;

    prep_weights<<<(40960 + 255) / 256, 256>>>(W0, W1, W2);
    mlp_kernel<<<ntiles, 256>>>(src, dst, edg, b0, b1, b2, (float*)d_out, E);
}